// round 16
// baseline (speedup 1.0000x reference)
#include <cuda_runtime.h>
#include <cuda_bf16.h>
#include <stdint.h>

#define Bsz 8
#define Tsz 4096
#define Csz 512
#define Msz (Bsz*Tsz)          // 32768 rows
#define BLsz (Bsz*Csz)         // 4096 scan lanes
#define NCH 64
#define LCH (Tsz/NCH)          // 64
#define NEG_INF -1e38f

// ---------------- static device scratch ----------------
__device__ __nv_bfloat16 g_xkhi[Msz*Csz], g_xklo[Msz*Csz];
__device__ __nv_bfloat16 g_xvhi[Msz*Csz], g_xvlo[Msz*Csz];
__device__ __nv_bfloat16 g_xrhi[Msz*Csz], g_xrlo[Msz*Csz];
__device__ __nv_bfloat16 g_yhi [Msz*Csz], g_ylo [Msz*Csz];
__device__ float g_k[Msz*Csz], g_v[Msz*Csz], g_r[Msz*Csz];
__device__ __nv_bfloat16 g_wthi[4][Csz*Csz], g_wtlo[4][Csz*Csz];   // [N,K] transposed
__device__ float g_sp[NCH*BLsz], g_sq[NCH*BLsz], g_so[NCH*BLsz];
__device__ float g_pp[NCH*BLsz], g_pq[NCH*BLsz], g_po[NCH*BLsz];

static __device__ __forceinline__ uint32_t smem_u32(const void* p) {
    uint32_t a;
    asm("{ .reg .u64 t; cvta.to.shared.u64 t, %1; cvt.u32.u64 %0, t; }" : "=r"(a) : "l"(p));
    return a;
}

#define LDSM4(r0,r1,r2,r3,addr) \
    asm volatile("ldmatrix.sync.aligned.m8n8.x4.shared.b16 {%0,%1,%2,%3}, [%4];" \
        : "=r"(r0),"=r"(r1),"=r"(r2),"=r"(r3) : "r"(addr))

#define MMA16816(c,a0,a1,a2,a3,b0,b1) \
    asm volatile("mma.sync.aligned.m16n8k16.row.col.f32.bf16.bf16.f32 " \
        "{%0,%1,%2,%3}, {%4,%5,%6,%7}, {%8,%9}, {%0,%1,%2,%3};" \
        : "+f"((c)[0]),"+f"((c)[1]),"+f"((c)[2]),"+f"((c)[3]) \
        : "r"(a0),"r"(a1),"r"(a2),"r"(a3),"r"(b0),"r"(b1))

#define CP16(dst, src) \
    asm volatile("cp.async.cg.shared.global [%0], [%1], 16;" :: "r"(dst), "l"(src))
#define CPCOMMIT() asm volatile("cp.async.commit_group;" ::: "memory")
#define CPWAIT0()  asm volatile("cp.async.wait_group 0;" ::: "memory")
#define CPWAIT1()  asm volatile("cp.async.wait_group 1;" ::: "memory")

// SW64 swizzle for 64B rows: XOR bits[5:4] with bits[8:7]
#define SW64(o) ((o) ^ (((o) >> 3) & 0x30))

// ---------------- split helper ----------------
static __device__ __forceinline__ void split_store4(float4 v, __nv_bfloat16* hi, __nv_bfloat16* lo) {
    ushort4 h, l;
    __nv_bfloat16 b;
    b = __float2bfloat16(v.x); h.x = __bfloat16_as_ushort(b);
    l.x = __bfloat16_as_ushort(__float2bfloat16(v.x - __bfloat162float(b)));
    b = __float2bfloat16(v.y); h.y = __bfloat16_as_ushort(b);
    l.y = __bfloat16_as_ushort(__float2bfloat16(v.y - __bfloat162float(b)));
    b = __float2bfloat16(v.z); h.z = __bfloat16_as_ushort(b);
    l.z = __bfloat16_as_ushort(__float2bfloat16(v.z - __bfloat162float(b)));
    b = __float2bfloat16(v.w); h.w = __bfloat16_as_ushort(b);
    l.w = __bfloat16_as_ushort(__float2bfloat16(v.w - __bfloat162float(b)));
    *(ushort4*)hi = h;
    *(ushort4*)lo = l;
}

// one-exp log-sum-exp step (bitwise-identical to the 2-exp version)
static __device__ __forceinline__ void exp2max(float a, float b,
                                               float& ea, float& eb, float& m) {
    bool ge = a >= b;
    float e = __expf(ge ? (b - a) : (a - b));
    m  = ge ? a : b;
    ea = ge ? 1.0f : e;
    eb = ge ? e : 1.0f;
}

// =====================================================================
// 1) time-shift + mix -> split-bf16 activations
// =====================================================================
__global__ void mix_kernel(const float* __restrict__ x,
                           const float* __restrict__ mk,
                           const float* __restrict__ mv,
                           const float* __restrict__ mr) {
    long gid = (long)blockIdx.x * blockDim.x + threadIdx.x;
    long e = gid * 4;
    if (e >= (long)Msz * Csz) return;
    int  c = (int)(e & (Csz - 1));
    long m = e >> 9;
    int  t = (int)(m & (Tsz - 1));
    float4 xc = *(const float4*)(x + e);
    float4 xp = make_float4(0.f, 0.f, 0.f, 0.f);
    if (t > 0) xp = *(const float4*)(x + e - Csz);
    float4 k4 = *(const float4*)(mk + c);
    float4 v4 = *(const float4*)(mv + c);
    float4 r4 = *(const float4*)(mr + c);
    float4 ok, ov, orr;
    ok.x = xc.x*k4.x + xp.x*(1.f-k4.x);  ok.y = xc.y*k4.y + xp.y*(1.f-k4.y);
    ok.z = xc.z*k4.z + xp.z*(1.f-k4.z);  ok.w = xc.w*k4.w + xp.w*(1.f-k4.w);
    ov.x = xc.x*v4.x + xp.x*(1.f-v4.x);  ov.y = xc.y*v4.y + xp.y*(1.f-v4.y);
    ov.z = xc.z*v4.z + xp.z*(1.f-v4.z);  ov.w = xc.w*v4.w + xp.w*(1.f-v4.w);
    orr.x = xc.x*r4.x + xp.x*(1.f-r4.x); orr.y = xc.y*r4.y + xp.y*(1.f-r4.y);
    orr.z = xc.z*r4.z + xp.z*(1.f-r4.z); orr.w = xc.w*r4.w + xp.w*(1.f-r4.w);
    split_store4(ok,  g_xkhi + e, g_xklo + e);
    split_store4(ov,  g_xvhi + e, g_xvlo + e);
    split_store4(orr, g_xrhi + e, g_xrlo + e);
}

// =====================================================================
// 2) weight prep: transpose [K,N]->[N,K] + bf16 split (4 matrices)
// =====================================================================
__global__ void prep_w(const float* __restrict__ w0, const float* __restrict__ w1,
                       const float* __restrict__ w2, const float* __restrict__ w3) {
    int gid = blockIdx.x * blockDim.x + threadIdx.x;
    int m = gid >> 18;
    int n = (gid >> 9) & 511;
    int k = gid & 511;
    const float* W = (m == 0) ? w0 : (m == 1) ? w1 : (m == 2) ? w2 : w3;
    float x = W[k * Csz + n];
    __nv_bfloat16 hb = __float2bfloat16(x);
    g_wthi[m][n * Csz + k] = hb;
    g_wtlo[m][n * Csz + k] = __float2bfloat16(x - __bfloat162float(hb));
}

// =====================================================================
// 3) fused split-bf16 HMMA GEMM (round-9 exact inner schedule).
//    CTA 128x128, 4 warps (2M x 2N), warp tile 64x64, SW64 smem,
//    3-stage cp.async pipeline, two barriers per K-slab.
// =====================================================================
#define BM 128
#define BN 128
#define NTHR 128
#define TBUF 8192                     // 128 rows x 64B, no pad (SW64)
#define STGB (4 * TBUF)               // 32768 B (Ahi,Alo,Bhi,Blo)
#define NSTG 3
#define DYNSM (NSTG * STGB)           // 98304 B

extern __shared__ char dynsm[];

__global__ void __launch_bounds__(NTHR, 2)
bgemm_f(int base, float* __restrict__ Cext) {
    int sel = base + (int)blockIdx.z;

    const __nv_bfloat16 *Ahi, *Alo, *Bhi, *Blo; float* C;
    switch (sel) {
      case 0:  Ahi = g_xkhi; Alo = g_xklo; Bhi = g_wthi[0]; Blo = g_wtlo[0]; C = g_k;  break;
      case 1:  Ahi = g_xvhi; Alo = g_xvlo; Bhi = g_wthi[1]; Blo = g_wtlo[1]; C = g_v;  break;
      case 2:  Ahi = g_xrhi; Alo = g_xrlo; Bhi = g_wthi[2]; Blo = g_wtlo[2]; C = g_r;  break;
      default: Ahi = g_yhi;  Alo = g_ylo;  Bhi = g_wthi[3]; Blo = g_wtlo[3]; C = Cext; break;
    }

    int tid = threadIdx.x, lid = tid & 31, wid = tid >> 5;
    int wm = wid & 1, wn = wid >> 1;                 // 2(M) x 2(N)
    int rowBase = blockIdx.y * BM, colBase = blockIdx.x * BN;

    uint32_t smb = smem_u32(dynsm);

    auto issue = [&](int i) {
        int k0 = i << 5;
        uint32_t st = smb + (uint32_t)((i % NSTG) * STGB);
        #pragma unroll
        for (int j = 0; j < 4; j++) {
            int g  = tid + NTHR * j;                 // 0..511 granules (16B)
            int gr = g >> 2, gc = g & 3;
            uint32_t d = SW64((uint32_t)(gr * 64 + gc * 16));
            size_t sa = (size_t)(rowBase + gr) * Csz + gc * 8 + k0;
            size_t sb = (size_t)(colBase + gr) * Csz + gc * 8 + k0;
            CP16(st + d,          Ahi + sa);
            CP16(st + TBUF + d,   Alo + sa);
            CP16(st + 2*TBUF + d, Bhi + sb);
            CP16(st + 3*TBUF + d, Blo + sb);
        }
        CPCOMMIT();
    };

    float acc[4][8][4];
    #pragma unroll
    for (int i = 0; i < 4; i++)
        #pragma unroll
        for (int j = 0; j < 8; j++)
            #pragma unroll
            for (int e = 0; e < 4; e++) acc[i][j][e] = 0.f;

    // ldmatrix addressing with SW64: row part additive, low 6 bits XORed
    uint32_t aRow0  = (uint32_t)(wm * 4096 + (lid & 15) * 64);
    uint32_t aSwamt = (aRow0 >> 3) & 0x30;
    uint32_t aLow   = (uint32_t)((lid >> 4) * 16);
    int      rowb   = (lid & 7) + ((lid >> 4) << 3);
    uint32_t bRow0  = (uint32_t)(wn * 4096 + rowb * 64);
    uint32_t bSwamt = ((uint32_t)(rowb * 64) >> 3) & 0x30;
    uint32_t bLow   = (uint32_t)(((lid >> 3) & 1) * 16);

    issue(0);
    issue(1);

    for (int it = 0; it < 16; it++) {
        if (it == 15) { CPWAIT0(); } else { CPWAIT1(); }
        __syncthreads();            // stage it visible to all
        if (it < 14) issue(it + 2); // stage (it+2)%3 last read at it-1

        uint32_t st = smb + (uint32_t)((it % NSTG) * STGB);
        #pragma unroll
        for (int kk2 = 0; kk2 < 2; kk2++) {
            uint32_t aL = ((uint32_t)(kk2 * 32) + aLow) ^ aSwamt;
            uint32_t bL = ((uint32_t)(kk2 * 32) + bLow) ^ bSwamt;
            uint32_t a[4][4], b[4][4], al[4][4];

            // ---- Ahi x Bhi ----
            #pragma unroll
            for (int mi = 0; mi < 4; mi++)
                LDSM4(a[mi][0], a[mi][1], a[mi][2], a[mi][3],
                      st + aRow0 + (uint32_t)(mi * 1024) + aL);
            #pragma unroll
            for (int g = 0; g < 4; g++)
                LDSM4(b[g][0], b[g][1], b[g][2], b[g][3],
                      st + 2*TBUF + bRow0 + (uint32_t)(g * 1024) + bL);
            #pragma unroll
            for (int mi = 0; mi < 4; mi++)
                #pragma unroll
                for (int ni = 0; ni < 8; ni++)
                    MMA16816(acc[mi][ni], a[mi][0], a[mi][1], a[mi][2], a[mi][3],
                             b[ni>>1][(ni&1)*2], b[ni>>1][(ni&1)*2+1]);

            // ---- Alo x Bhi ----
            #pragma unroll
            for (int mi = 0; mi < 4; mi++)
                LDSM4(al[mi][0], al[mi][1], al[mi][2], al[mi][3],
                      st + TBUF + aRow0 + (uint32_t)(mi * 1024) + aL);
            #pragma unroll
            for (int mi = 0; mi < 4; mi++)
                #pragma unroll
                for (int ni = 0; ni < 8; ni++)
                    MMA16816(acc[mi][ni], al[mi][0], al[mi][1], al[mi][2], al[mi][3],
                             b[ni>>1][(ni&1)*2], b[ni>>1][(ni&1)*2+1]);

            // ---- Ahi x Blo (reuse b regs) ----
            #pragma unroll
            for (int g = 0; g < 4; g++)
                LDSM4(b[g][0], b[g][1], b[g][2], b[g][3],
                      st + 3*TBUF + bRow0 + (uint32_t)(g * 1024) + bL);
            #pragma unroll
            for (int mi = 0; mi < 4; mi++)
                #pragma unroll
                for (int ni = 0; ni < 8; ni++)
                    MMA16816(acc[mi][ni], a[mi][0], a[mi][1], a[mi][2], a[mi][3],
                             b[ni>>1][(ni&1)*2], b[ni>>1][(ni&1)*2+1]);
        }
        __syncthreads();
    }

    // epilogue
    int lr = lid >> 2, lc = (lid & 3) * 2;
    #pragma unroll
    for (int mi = 0; mi < 4; mi++) {
        #pragma unroll
        for (int ni = 0; ni < 8; ni++) {
            int row = rowBase + wm * 64 + mi * 16 + lr;
            int col = colBase + wn * 64 + ni * 8 + lc;
            *(float2*)(C + (size_t)row * Csz + col)       = make_float2(acc[mi][ni][0], acc[mi][ni][1]);
            *(float2*)(C + (size_t)(row + 8) * Csz + col) = make_float2(acc[mi][ni][2], acc[mi][ni][3]);
        }
    }
}

// =====================================================================
// 4) WKV chunked scan (NCH=64, 3 kernels) with register-prefetched
//    loads (iteration i+1's k/v/r issued before computing iteration i).
// =====================================================================
__global__ void wkv_pass1(const float* __restrict__ sd) {
    int tid = threadIdx.x;
    int bid = blockIdx.x;
    const int CB = Csz / 256;
    int cblk = bid % CB;
    int j    = (bid / CB) % NCH;
    int b    = bid / (CB * NCH);
    int c    = cblk * 256 + tid;
    int lane = b * Csz + c;

    float w = sd[c] * (1.0f / Tsz);
    size_t base = ((size_t)b * Tsz + (size_t)j * LCH) * Csz + c;
    const float* kp = g_k + base;
    const float* vp = g_v + base;

    float p = 0.f, q = 0.f, o = NEG_INF;
    float kt = kp[0], vt = vp[0];
    #pragma unroll 4
    for (int i = 0; i < LCH; i++) {
        float kn = 0.f, vn = 0.f;
        if (i + 1 < LCH) {                    // prefetch next step
            kn = kp[(i + 1) * Csz];
            vn = vp[(i + 1) * Csz];
        }
        float A, Bv, no;
        exp2max(w + o, kt, A, Bv, no);
        p = A * p + Bv * vt;
        q = A * q + Bv;
        o = no;
        kt = kn; vt = vn;
    }
    g_sp[j * BLsz + lane] = p;
    g_sq[j * BLsz + lane] = q;
    g_so[j * BLsz + lane] = o;
}

__global__ void wkv_combine(const float* __restrict__ sd) {
    int lane = blockIdx.x * blockDim.x + threadIdx.x;
    int c = lane & (Csz - 1);
    float w  = sd[c] * (1.0f / Tsz);
    float wl = w * (float)LCH;
    float p = 0.f, q = 0.f, o = NEG_INF;
    for (int j = 0; j < NCH; j++) {
        g_pp[j * BLsz + lane] = p;
        g_pq[j * BLsz + lane] = q;
        g_po[j * BLsz + lane] = o;
        float pc = g_sp[j * BLsz + lane];
        float qc = g_sq[j * BLsz + lane];
        float oc = g_so[j * BLsz + lane];
        float e1, e2, m;
        exp2max(o + wl, oc, e1, e2, m);
        p = e1 * p + e2 * pc;
        q = e1 * q + e2 * qc;
        o = m;
    }
}

__global__ void wkv_pass2(const float* __restrict__ sd, const float* __restrict__ sf) {
    int tid = threadIdx.x;
    int bid = blockIdx.x;
    const int CB = Csz / 256;
    int cblk = bid % CB;
    int j    = (bid / CB) % NCH;
    int b    = bid / (CB * NCH);
    int c    = cblk * 256 + tid;
    int lane = b * Csz + c;

    float w = sd[c] * (1.0f / Tsz);
    float u = sf[c] * (1.0f / Tsz);

    float p = g_pp[j * BLsz + lane];
    float q = g_pq[j * BLsz + lane];
    float o = g_po[j * BLsz + lane];

    size_t base = ((size_t)b * Tsz + (size_t)j * LCH) * Csz + c;
    const float* kp = g_k + base;
    const float* vp = g_v + base;
    const float* rp = g_r + base;

    float kt = kp[0], vt = vp[0], rt = rp[0];
    #pragma unroll 2
    for (int i = 0; i < LCH; i++) {
        float kn = 0.f, vn = 0.f, rn = 0.f;
        if (i + 1 < LCH) {                    // prefetch next step
            kn = kp[(i + 1) * Csz];
            vn = vp[(i + 1) * Csz];
            rn = rp[(i + 1) * Csz];
        }
        float A, Bt, no;
        exp2max(o, u + kt, A, Bt, no);
        float num = A * p + Bt * vt;
        float den = A * q + Bt;
        float sy = __fdividef(num, den * (1.0f + __expf(-rt)));
        __nv_bfloat16 hb = __float2bfloat16(sy);
        g_yhi[base + (size_t)i * Csz] = hb;
        g_ylo[base + (size_t)i * Csz] = __float2bfloat16(sy - __bfloat162float(hb));
        float A2, B2, no2;
        exp2max(w + o, kt, A2, B2, no2);
        p = A2 * p + B2 * vt;
        q = A2 * q + B2;
        o = no2;
        kt = kn; vt = vn; rt = rn;
    }
}

// =====================================================================
// launch: dual-stream graph. kv-GEMM launched BEFORE r-GEMM so kv's
// CTAs dispatch first -> kv drains early -> pass1+combine (DRAM-bound)
// co-run with the r-GEMM tail (tensor-bound).
//   s2:   prep_w ............ r-GEMM
//   main: mix -> kv-GEMM -> pass1 -> combine -> [join r] -> pass2 -> out-GEMM
// =====================================================================
extern "C" void kernel_launch(void* const* d_in, const int* in_sizes, int n_in,
                              void* d_out, int out_size) {
    const float* x  = (const float*)d_in[0];
    const float* sd = (const float*)d_in[1];
    const float* sf = (const float*)d_in[2];
    const float* mk = (const float*)d_in[3];
    const float* mv = (const float*)d_in[4];
    const float* mr = (const float*)d_in[5];
    const float* wk = (const float*)d_in[6];
    const float* wv = (const float*)d_in[7];
    const float* wr = (const float*)d_in[8];
    const float* wo = (const float*)d_in[9];
    float* out = (float*)d_out;

    static int inited = 0;
    static cudaStream_t s2;
    static cudaEvent_t evFork, evPrep, evMix, evR;
    if (!inited) {
        cudaFuncSetAttribute(bgemm_f, cudaFuncAttributeMaxDynamicSharedMemorySize, DYNSM);
        cudaStreamCreateWithFlags(&s2, cudaStreamNonBlocking);
        cudaEventCreateWithFlags(&evFork, cudaEventDisableTiming);
        cudaEventCreateWithFlags(&evPrep, cudaEventDisableTiming);
        cudaEventCreateWithFlags(&evMix,  cudaEventDisableTiming);
        cudaEventCreateWithFlags(&evR,    cudaEventDisableTiming);
        inited = 1;
    }

    dim3 grid_kv(Csz / BN, Msz / BM, 2);   // k, v
    dim3 grid_1 (Csz / BN, Msz / BM, 1);   // r / out

    // fork s2 from main
    cudaEventRecord(evFork, 0);
    cudaStreamWaitEvent(s2, evFork, 0);

    prep_w<<<(4 * Csz * Csz) / 256, 256, 0, s2>>>(wk, wv, wr, wo);
    cudaEventRecord(evPrep, s2);

    mix_kernel<<<(Msz * Csz / 4 + 255) / 256, 256>>>(x, mk, mv, mr);
    cudaStreamWaitEvent(0, evPrep, 0);      // main: weights ready before kv-GEMM
    cudaEventRecord(evMix, 0);              // mix (and prep) done
    cudaStreamWaitEvent(s2, evMix, 0);      // s2: r-GEMM needs mix output

    // kv-GEMM first: its CTAs dispatch ahead of r's, so kv drains early
    bgemm_f<<<grid_kv, NTHR, DYNSM>>>(0, nullptr);      // k, v on main
    bgemm_f<<<grid_1, NTHR, DYNSM, s2>>>(2, nullptr);   // r GEMM on s2
    cudaEventRecord(evR, s2);

    wkv_pass1 <<<Bsz * NCH * (Csz / 256), 256>>>(sd);   // overlaps r-GEMM tail
    wkv_combine<<<BLsz / 256, 256>>>(sd);

    cudaStreamWaitEvent(0, evR, 0);                     // join: r ready
    wkv_pass2 <<<Bsz * NCH * (Csz / 256), 256>>>(sd, sf);

    bgemm_f<<<grid_1, NTHR, DYNSM>>>(3, out);           // out = (sr*y) @ wo
}

// round 17
// speedup vs baseline: 1.5839x; 1.5839x over previous
#include <cuda_runtime.h>
#include <cuda_bf16.h>
#include <cuda_fp16.h>
#include <stdint.h>

#define Bsz 8
#define Tsz 4096
#define Csz 512
#define Msz (Bsz*Tsz)          // 32768 rows
#define BLsz (Bsz*Csz)         // 4096 scan lanes
#define NCH 64
#define LCH (Tsz/NCH)          // 64
#define NEG_INF -1e38f

// ---------------- static device scratch ----------------
__device__ __half g_xk16[Msz*Csz], g_xv16[Msz*Csz], g_xr16[Msz*Csz];
__device__ __half g_w16[3][Csz*Csz];                               // k,v,r weights [N,K] fp16
__device__ __nv_bfloat16 g_yhi[Msz*Csz], g_ylo[Msz*Csz];
__device__ __nv_bfloat16 g_wohi[Csz*Csz], g_wolo[Csz*Csz];         // wo split [N,K]
__device__ float g_k[Msz*Csz], g_v[Msz*Csz], g_r[Msz*Csz];
__device__ float g_sp[NCH*BLsz], g_sq[NCH*BLsz], g_so[NCH*BLsz];
__device__ float g_pp[NCH*BLsz], g_pq[NCH*BLsz], g_po[NCH*BLsz];

static __device__ __forceinline__ uint32_t smem_u32(const void* p) {
    uint32_t a;
    asm("{ .reg .u64 t; cvta.to.shared.u64 t, %1; cvt.u32.u64 %0, t; }" : "=r"(a) : "l"(p));
    return a;
}

#define LDSM4(r0,r1,r2,r3,addr) \
    asm volatile("ldmatrix.sync.aligned.m8n8.x4.shared.b16 {%0,%1,%2,%3}, [%4];" \
        : "=r"(r0),"=r"(r1),"=r"(r2),"=r"(r3) : "r"(addr))

#define MMA16816BF(c,a0,a1,a2,a3,b0,b1) \
    asm volatile("mma.sync.aligned.m16n8k16.row.col.f32.bf16.bf16.f32 " \
        "{%0,%1,%2,%3}, {%4,%5,%6,%7}, {%8,%9}, {%0,%1,%2,%3};" \
        : "+f"((c)[0]),"+f"((c)[1]),"+f"((c)[2]),"+f"((c)[3]) \
        : "r"(a0),"r"(a1),"r"(a2),"r"(a3),"r"(b0),"r"(b1))

#define MMA16816FP(c,a0,a1,a2,a3,b0,b1) \
    asm volatile("mma.sync.aligned.m16n8k16.row.col.f32.f16.f16.f32 " \
        "{%0,%1,%2,%3}, {%4,%5,%6,%7}, {%8,%9}, {%0,%1,%2,%3};" \
        : "+f"((c)[0]),"+f"((c)[1]),"+f"((c)[2]),"+f"((c)[3]) \
        : "r"(a0),"r"(a1),"r"(a2),"r"(a3),"r"(b0),"r"(b1))

#define CP16(dst, src) \
    asm volatile("cp.async.cg.shared.global [%0], [%1], 16;" :: "r"(dst), "l"(src))
#define CPCOMMIT() asm volatile("cp.async.commit_group;" ::: "memory")
#define CPWAIT0()  asm volatile("cp.async.wait_group 0;" ::: "memory")
#define CPWAIT1()  asm volatile("cp.async.wait_group 1;" ::: "memory")

// SW64 swizzle for 64B rows: XOR bits[5:4] with bits[8:7]
#define SW64(o) ((o) ^ (((o) >> 3) & 0x30))

// one-exp log-sum-exp step (bitwise-identical to the 2-exp version)
static __device__ __forceinline__ void exp2max(float a, float b,
                                               float& ea, float& eb, float& m) {
    bool ge = a >= b;
    float e = __expf(ge ? (b - a) : (a - b));
    m  = ge ? a : b;
    ea = ge ? 1.0f : e;
    eb = ge ? e : 1.0f;
}

static __device__ __forceinline__ ushort4 half4_pack(float4 v) {
    ushort4 h;
    h.x = __half_as_ushort(__float2half_rn(v.x));
    h.y = __half_as_ushort(__float2half_rn(v.y));
    h.z = __half_as_ushort(__float2half_rn(v.z));
    h.w = __half_as_ushort(__float2half_rn(v.w));
    return h;
}

// =====================================================================
// 1) time-shift + mix -> fp16 activations (single precision level)
// =====================================================================
__global__ void mix_kernel(const float* __restrict__ x,
                           const float* __restrict__ mk,
                           const float* __restrict__ mv,
                           const float* __restrict__ mr) {
    long gid = (long)blockIdx.x * blockDim.x + threadIdx.x;
    long e = gid * 4;
    if (e >= (long)Msz * Csz) return;
    int  c = (int)(e & (Csz - 1));
    long m = e >> 9;
    int  t = (int)(m & (Tsz - 1));
    float4 xc = *(const float4*)(x + e);
    float4 xp = make_float4(0.f, 0.f, 0.f, 0.f);
    if (t > 0) xp = *(const float4*)(x + e - Csz);
    float4 k4 = *(const float4*)(mk + c);
    float4 v4 = *(const float4*)(mv + c);
    float4 r4 = *(const float4*)(mr + c);
    float4 ok, ov, orr;
    ok.x = xc.x*k4.x + xp.x*(1.f-k4.x);  ok.y = xc.y*k4.y + xp.y*(1.f-k4.y);
    ok.z = xc.z*k4.z + xp.z*(1.f-k4.z);  ok.w = xc.w*k4.w + xp.w*(1.f-k4.w);
    ov.x = xc.x*v4.x + xp.x*(1.f-v4.x);  ov.y = xc.y*v4.y + xp.y*(1.f-v4.y);
    ov.z = xc.z*v4.z + xp.z*(1.f-v4.z);  ov.w = xc.w*v4.w + xp.w*(1.f-v4.w);
    orr.x = xc.x*r4.x + xp.x*(1.f-r4.x); orr.y = xc.y*r4.y + xp.y*(1.f-r4.y);
    orr.z = xc.z*r4.z + xp.z*(1.f-r4.z); orr.w = xc.w*r4.w + xp.w*(1.f-r4.w);
    *(ushort4*)(g_xk16 + e) = half4_pack(ok);
    *(ushort4*)(g_xv16 + e) = half4_pack(ov);
    *(ushort4*)(g_xr16 + e) = half4_pack(orr);
}

// =====================================================================
// 2) weight prep: transpose [K,N]->[N,K]; k/v/r fp16, wo bf16-split
// =====================================================================
__global__ void prep_w(const float* __restrict__ w0, const float* __restrict__ w1,
                       const float* __restrict__ w2, const float* __restrict__ w3) {
    int gid = blockIdx.x * blockDim.x + threadIdx.x;
    int m = gid >> 18;
    int n = (gid >> 9) & 511;
    int k = gid & 511;
    if (m < 3) {
        const float* W = (m == 0) ? w0 : (m == 1) ? w1 : w2;
        g_w16[m][n * Csz + k] = __float2half_rn(W[k * Csz + n]);
    } else {
        float x = w3[k * Csz + n];
        __nv_bfloat16 hb = __float2bfloat16(x);
        g_wohi[n * Csz + k] = hb;
        g_wolo[n * Csz + k] = __float2bfloat16(x - __bfloat162float(hb));
    }
}

// =====================================================================
// 3a) fp16 single-pass HMMA GEMM for k/v/r. CTA 128x128, 4 warps,
//     warp tile 64x64, SW64 smem, 3-stage cp.async, K=512 (16 slabs).
// =====================================================================
#define BM 128
#define BN 128
#define NTHR 128
#define TBUF 8192                     // 128 rows x 64B (32 fp16/bf16 elems)
#define NSTG 3

extern __shared__ char dynsm[];

#define HSTGB (2 * TBUF)              // 16384 B (A, B)
#define HDYNSM (NSTG * HSTGB)         // 49152 B

__global__ void __launch_bounds__(NTHR, 2)
hgemm_f(int base) {
    int sel = base + (int)blockIdx.z;
    const __half *A, *B; float* C;
    switch (sel) {
      case 0:  A = g_xk16; B = g_w16[0]; C = g_k; break;
      case 1:  A = g_xv16; B = g_w16[1]; C = g_v; break;
      default: A = g_xr16; B = g_w16[2]; C = g_r; break;
    }

    int tid = threadIdx.x, lid = tid & 31, wid = tid >> 5;
    int wm = wid & 1, wn = wid >> 1;
    int rowBase = blockIdx.y * BM, colBase = blockIdx.x * BN;

    uint32_t smb = smem_u32(dynsm);

    auto issue = [&](int i) {
        int k0 = i << 5;
        uint32_t st = smb + (uint32_t)((i % NSTG) * HSTGB);
        #pragma unroll
        for (int j = 0; j < 4; j++) {
            int g  = tid + NTHR * j;
            int gr = g >> 2, gc = g & 3;
            uint32_t d = SW64((uint32_t)(gr * 64 + gc * 16));
            size_t sa = (size_t)(rowBase + gr) * Csz + gc * 8 + k0;
            size_t sb = (size_t)(colBase + gr) * Csz + gc * 8 + k0;
            CP16(st + d,        A + sa);
            CP16(st + TBUF + d, B + sb);
        }
        CPCOMMIT();
    };

    float acc[4][8][4];
    #pragma unroll
    for (int i = 0; i < 4; i++)
        #pragma unroll
        for (int j = 0; j < 8; j++)
            #pragma unroll
            for (int e = 0; e < 4; e++) acc[i][j][e] = 0.f;

    uint32_t aRow0  = (uint32_t)(wm * 4096 + (lid & 15) * 64);
    uint32_t aSwamt = (aRow0 >> 3) & 0x30;
    uint32_t aLow   = (uint32_t)((lid >> 4) * 16);
    int      rowb   = (lid & 7) + ((lid >> 4) << 3);
    uint32_t bRow0  = (uint32_t)(wn * 4096 + rowb * 64);
    uint32_t bSwamt = ((uint32_t)(rowb * 64) >> 3) & 0x30;
    uint32_t bLow   = (uint32_t)(((lid >> 3) & 1) * 16);

    issue(0);
    issue(1);

    for (int it = 0; it < 16; it++) {
        if (it == 15) { CPWAIT0(); } else { CPWAIT1(); }
        __syncthreads();
        if (it < 14) issue(it + 2);

        uint32_t st = smb + (uint32_t)((it % NSTG) * HSTGB);
        #pragma unroll
        for (int kk2 = 0; kk2 < 2; kk2++) {
            uint32_t aL = ((uint32_t)(kk2 * 32) + aLow) ^ aSwamt;
            uint32_t bL = ((uint32_t)(kk2 * 32) + bLow) ^ bSwamt;
            uint32_t a[4][4], b[4][4];
            #pragma unroll
            for (int mi = 0; mi < 4; mi++)
                LDSM4(a[mi][0], a[mi][1], a[mi][2], a[mi][3],
                      st + aRow0 + (uint32_t)(mi * 1024) + aL);
            #pragma unroll
            for (int g = 0; g < 4; g++)
                LDSM4(b[g][0], b[g][1], b[g][2], b[g][3],
                      st + TBUF + bRow0 + (uint32_t)(g * 1024) + bL);
            #pragma unroll
            for (int mi = 0; mi < 4; mi++)
                #pragma unroll
                for (int ni = 0; ni < 8; ni++)
                    MMA16816FP(acc[mi][ni], a[mi][0], a[mi][1], a[mi][2], a[mi][3],
                               b[ni>>1][(ni&1)*2], b[ni>>1][(ni&1)*2+1]);
        }
        __syncthreads();
    }

    int lr = lid >> 2, lc = (lid & 3) * 2;
    #pragma unroll
    for (int mi = 0; mi < 4; mi++) {
        #pragma unroll
        for (int ni = 0; ni < 8; ni++) {
            int row = rowBase + wm * 64 + mi * 16 + lr;
            int col = colBase + wn * 64 + ni * 8 + lc;
            *(float2*)(C + (size_t)row * Csz + col)       = make_float2(acc[mi][ni][0], acc[mi][ni][1]);
            *(float2*)(C + (size_t)(row + 8) * Csz + col) = make_float2(acc[mi][ni][2], acc[mi][ni][3]);
        }
    }
}

// =====================================================================
// 3b) split-bf16 output GEMM (round-9 exact): out = y @ wo, eff K=1536
// =====================================================================
#define STGB (4 * TBUF)               // 32768 B (Ahi,Alo,Bhi,Blo)
#define DYNSM (NSTG * STGB)           // 98304 B

__global__ void __launch_bounds__(NTHR, 2)
bgemm_out(float* __restrict__ Cext) {
    const __nv_bfloat16 *Ahi = g_yhi, *Alo = g_ylo, *Bhi = g_wohi, *Blo = g_wolo;
    float* C = Cext;

    int tid = threadIdx.x, lid = tid & 31, wid = tid >> 5;
    int wm = wid & 1, wn = wid >> 1;
    int rowBase = blockIdx.y * BM, colBase = blockIdx.x * BN;

    uint32_t smb = smem_u32(dynsm);

    auto issue = [&](int i) {
        int k0 = i << 5;
        uint32_t st = smb + (uint32_t)((i % NSTG) * STGB);
        #pragma unroll
        for (int j = 0; j < 4; j++) {
            int g  = tid + NTHR * j;
            int gr = g >> 2, gc = g & 3;
            uint32_t d = SW64((uint32_t)(gr * 64 + gc * 16));
            size_t sa = (size_t)(rowBase + gr) * Csz + gc * 8 + k0;
            size_t sb = (size_t)(colBase + gr) * Csz + gc * 8 + k0;
            CP16(st + d,          Ahi + sa);
            CP16(st + TBUF + d,   Alo + sa);
            CP16(st + 2*TBUF + d, Bhi + sb);
            CP16(st + 3*TBUF + d, Blo + sb);
        }
        CPCOMMIT();
    };

    float acc[4][8][4];
    #pragma unroll
    for (int i = 0; i < 4; i++)
        #pragma unroll
        for (int j = 0; j < 8; j++)
            #pragma unroll
            for (int e = 0; e < 4; e++) acc[i][j][e] = 0.f;

    uint32_t aRow0  = (uint32_t)(wm * 4096 + (lid & 15) * 64);
    uint32_t aSwamt = (aRow0 >> 3) & 0x30;
    uint32_t aLow   = (uint32_t)((lid >> 4) * 16);
    int      rowb   = (lid & 7) + ((lid >> 4) << 3);
    uint32_t bRow0  = (uint32_t)(wn * 4096 + rowb * 64);
    uint32_t bSwamt = ((uint32_t)(rowb * 64) >> 3) & 0x30;
    uint32_t bLow   = (uint32_t)(((lid >> 3) & 1) * 16);

    issue(0);
    issue(1);

    for (int it = 0; it < 16; it++) {
        if (it == 15) { CPWAIT0(); } else { CPWAIT1(); }
        __syncthreads();
        if (it < 14) issue(it + 2);

        uint32_t st = smb + (uint32_t)((it % NSTG) * STGB);
        #pragma unroll
        for (int kk2 = 0; kk2 < 2; kk2++) {
            uint32_t aL = ((uint32_t)(kk2 * 32) + aLow) ^ aSwamt;
            uint32_t bL = ((uint32_t)(kk2 * 32) + bLow) ^ bSwamt;
            uint32_t a[4][4], b[4][4], al[4][4];

            #pragma unroll
            for (int mi = 0; mi < 4; mi++)
                LDSM4(a[mi][0], a[mi][1], a[mi][2], a[mi][3],
                      st + aRow0 + (uint32_t)(mi * 1024) + aL);
            #pragma unroll
            for (int g = 0; g < 4; g++)
                LDSM4(b[g][0], b[g][1], b[g][2], b[g][3],
                      st + 2*TBUF + bRow0 + (uint32_t)(g * 1024) + bL);
            #pragma unroll
            for (int mi = 0; mi < 4; mi++)
                #pragma unroll
                for (int ni = 0; ni < 8; ni++)
                    MMA16816BF(acc[mi][ni], a[mi][0], a[mi][1], a[mi][2], a[mi][3],
                               b[ni>>1][(ni&1)*2], b[ni>>1][(ni&1)*2+1]);

            #pragma unroll
            for (int mi = 0; mi < 4; mi++)
                LDSM4(al[mi][0], al[mi][1], al[mi][2], al[mi][3],
                      st + TBUF + aRow0 + (uint32_t)(mi * 1024) + aL);
            #pragma unroll
            for (int mi = 0; mi < 4; mi++)
                #pragma unroll
                for (int ni = 0; ni < 8; ni++)
                    MMA16816BF(acc[mi][ni], al[mi][0], al[mi][1], al[mi][2], al[mi][3],
                               b[ni>>1][(ni&1)*2], b[ni>>1][(ni&1)*2+1]);

            #pragma unroll
            for (int g = 0; g < 4; g++)
                LDSM4(b[g][0], b[g][1], b[g][2], b[g][3],
                      st + 3*TBUF + bRow0 + (uint32_t)(g * 1024) + bL);
            #pragma unroll
            for (int mi = 0; mi < 4; mi++)
                #pragma unroll
                for (int ni = 0; ni < 8; ni++)
                    MMA16816BF(acc[mi][ni], a[mi][0], a[mi][1], a[mi][2], a[mi][3],
                               b[ni>>1][(ni&1)*2], b[ni>>1][(ni&1)*2+1]);
        }
        __syncthreads();
    }

    int lr = lid >> 2, lc = (lid & 3) * 2;
    #pragma unroll
    for (int mi = 0; mi < 4; mi++) {
        #pragma unroll
        for (int ni = 0; ni < 8; ni++) {
            int row = rowBase + wm * 64 + mi * 16 + lr;
            int col = colBase + wn * 64 + ni * 8 + lc;
            *(float2*)(C + (size_t)row * Csz + col)       = make_float2(acc[mi][ni][0], acc[mi][ni][1]);
            *(float2*)(C + (size_t)(row + 8) * Csz + col) = make_float2(acc[mi][ni][2], acc[mi][ni][3]);
        }
    }
}

// =====================================================================
// 4) WKV chunked scan (round-15 exact, with load prefetch)
// =====================================================================
__global__ void wkv_pass1(const float* __restrict__ sd) {
    int tid = threadIdx.x;
    int bid = blockIdx.x;
    const int CB = Csz / 256;
    int cblk = bid % CB;
    int j    = (bid / CB) % NCH;
    int b    = bid / (CB * NCH);
    int c    = cblk * 256 + tid;
    int lane = b * Csz + c;

    float w = sd[c] * (1.0f / Tsz);
    size_t base = ((size_t)b * Tsz + (size_t)j * LCH) * Csz + c;
    const float* kp = g_k + base;
    const float* vp = g_v + base;

    float p = 0.f, q = 0.f, o = NEG_INF;
    float kt = kp[0], vt = vp[0];
    #pragma unroll 4
    for (int i = 0; i < LCH; i++) {
        float kn = 0.f, vn = 0.f;
        if (i + 1 < LCH) {
            kn = kp[(i + 1) * Csz];
            vn = vp[(i + 1) * Csz];
        }
        float A, Bv, no;
        exp2max(w + o, kt, A, Bv, no);
        p = A * p + Bv * vt;
        q = A * q + Bv;
        o = no;
        kt = kn; vt = vn;
    }
    g_sp[j * BLsz + lane] = p;
    g_sq[j * BLsz + lane] = q;
    g_so[j * BLsz + lane] = o;
}

__global__ void wkv_combine(const float* __restrict__ sd) {
    int lane = blockIdx.x * blockDim.x + threadIdx.x;
    int c = lane & (Csz - 1);
    float w  = sd[c] * (1.0f / Tsz);
    float wl = w * (float)LCH;
    float p = 0.f, q = 0.f, o = NEG_INF;
    for (int j = 0; j < NCH; j++) {
        g_pp[j * BLsz + lane] = p;
        g_pq[j * BLsz + lane] = q;
        g_po[j * BLsz + lane] = o;
        float pc = g_sp[j * BLsz + lane];
        float qc = g_sq[j * BLsz + lane];
        float oc = g_so[j * BLsz + lane];
        float e1, e2, m;
        exp2max(o + wl, oc, e1, e2, m);
        p = e1 * p + e2 * pc;
        q = e1 * q + e2 * qc;
        o = m;
    }
}

__global__ void wkv_pass2(const float* __restrict__ sd, const float* __restrict__ sf) {
    int tid = threadIdx.x;
    int bid = blockIdx.x;
    const int CB = Csz / 256;
    int cblk = bid % CB;
    int j    = (bid / CB) % NCH;
    int b    = bid / (CB * NCH);
    int c    = cblk * 256 + tid;
    int lane = b * Csz + c;

    float w = sd[c] * (1.0f / Tsz);
    float u = sf[c] * (1.0f / Tsz);

    float p = g_pp[j * BLsz + lane];
    float q = g_pq[j * BLsz + lane];
    float o = g_po[j * BLsz + lane];

    size_t base = ((size_t)b * Tsz + (size_t)j * LCH) * Csz + c;
    const float* kp = g_k + base;
    const float* vp = g_v + base;
    const float* rp = g_r + base;

    float kt = kp[0], vt = vp[0], rt = rp[0];
    #pragma unroll 2
    for (int i = 0; i < LCH; i++) {
        float kn = 0.f, vn = 0.f, rn = 0.f;
        if (i + 1 < LCH) {
            kn = kp[(i + 1) * Csz];
            vn = vp[(i + 1) * Csz];
            rn = rp[(i + 1) * Csz];
        }
        float A, Bt, no;
        exp2max(o, u + kt, A, Bt, no);
        float num = A * p + Bt * vt;
        float den = A * q + Bt;
        float sy = __fdividef(num, den * (1.0f + __expf(-rt)));
        __nv_bfloat16 hb = __float2bfloat16(sy);
        g_yhi[base + (size_t)i * Csz] = hb;
        g_ylo[base + (size_t)i * Csz] = __float2bfloat16(sy - __bfloat162float(hb));
        float A2, B2, no2;
        exp2max(w + o, kt, A2, B2, no2);
        p = A2 * p + B2 * vt;
        q = A2 * q + B2;
        o = no2;
        kt = kn; vt = vn; rt = rn;
    }
}

// =====================================================================
// launch: round-15 exact schedule (r-GEMM launched first on s2).
//   s2:   prep_w .... r-hgemm (overlaps kv + pass1 + combine)
//   main: mix -> kv-hgemm -> pass1 -> combine -> [join r] -> pass2 -> out
// =====================================================================
extern "C" void kernel_launch(void* const* d_in, const int* in_sizes, int n_in,
                              void* d_out, int out_size) {
    const float* x  = (const float*)d_in[0];
    const float* sd = (const float*)d_in[1];
    const float* sf = (const float*)d_in[2];
    const float* mk = (const float*)d_in[3];
    const float* mv = (const float*)d_in[4];
    const float* mr = (const float*)d_in[5];
    const float* wk = (const float*)d_in[6];
    const float* wv = (const float*)d_in[7];
    const float* wr = (const float*)d_in[8];
    const float* wo = (const float*)d_in[9];
    float* out = (float*)d_out;

    static int inited = 0;
    static cudaStream_t s2;
    static cudaEvent_t evFork, evPrep, evMix, evR;
    if (!inited) {
        cudaFuncSetAttribute(hgemm_f,   cudaFuncAttributeMaxDynamicSharedMemorySize, HDYNSM);
        cudaFuncSetAttribute(bgemm_out, cudaFuncAttributeMaxDynamicSharedMemorySize, DYNSM);
        cudaStreamCreateWithFlags(&s2, cudaStreamNonBlocking);
        cudaEventCreateWithFlags(&evFork, cudaEventDisableTiming);
        cudaEventCreateWithFlags(&evPrep, cudaEventDisableTiming);
        cudaEventCreateWithFlags(&evMix,  cudaEventDisableTiming);
        cudaEventCreateWithFlags(&evR,    cudaEventDisableTiming);
        inited = 1;
    }

    dim3 grid_kv(Csz / BN, Msz / BM, 2);   // k, v
    dim3 grid_1 (Csz / BN, Msz / BM, 1);   // r / out

    cudaEventRecord(evFork, 0);
    cudaStreamWaitEvent(s2, evFork, 0);

    prep_w<<<(4 * Csz * Csz) / 256, 256, 0, s2>>>(wk, wv, wr, wo);
    cudaEventRecord(evPrep, s2);

    mix_kernel<<<(Msz * Csz / 4 + 255) / 256, 256>>>(x, mk, mv, mr);
    cudaStreamWaitEvent(0, evPrep, 0);
    cudaEventRecord(evMix, 0);
    cudaStreamWaitEvent(s2, evMix, 0);

    hgemm_f<<<grid_1, NTHR, HDYNSM, s2>>>(2);          // r GEMM on s2 (first)
    cudaEventRecord(evR, s2);

    hgemm_f<<<grid_kv, NTHR, HDYNSM>>>(0);             // k, v on main

    wkv_pass1 <<<Bsz * NCH * (Csz / 256), 256>>>(sd);  // overlaps r tail
    wkv_combine<<<BLsz / 256, 256>>>(sd);

    cudaStreamWaitEvent(0, evR, 0);                    // join: r ready
    wkv_pass2 <<<Bsz * NCH * (Csz / 256), 256>>>(sd, sf);

    bgemm_out<<<grid_1, NTHR, DYNSM>>>(out);           // out = (sr*y) @ wo
}